// round 3
// baseline (speedup 1.0000x reference)
#include <cuda_runtime.h>
#include <cuda_bf16.h>
#include <math.h>
#include <stdint.h>

#define S_SEG 256
#define WSTRIDE 68   // uint2 stride for packed [128 x 64-pair] tiles

// ---- global scratch (no allocs allowed) ----
__device__ uint2 g_lW1p[128 * WSTRIDE];
__device__ uint2 g_lW2p[128 * WSTRIDE];
__device__ uint2 g_gW1p[128 * WSTRIDE];
__device__ uint2 g_gW2p[128 * WSTRIDE];
__device__ float g_psum[S_SEG * 128];
__device__ float g_cnt[S_SEG];
__device__ float g_pooled[S_SEG * 128];

struct SmemT {
    uint2 Xp[128 * WSTRIDE];    // X packed; later reused as float Y[128*136]
    uint2 W1p[128 * WSTRIDE];   // W1 packed; later reused as H packed
    uint2 W2p[128 * WSTRIDE];
    float b1[128];
    float b2[128];
    int   seg[128];
};  // 210432 bytes

__device__ __forceinline__ void split2(float a, float b, uint32_t& hi, uint32_t& lo) {
    __nv_bfloat16 ah = __float2bfloat16(a);
    __nv_bfloat16 bh = __float2bfloat16(b);
    __nv_bfloat16 al = __float2bfloat16(a - __bfloat162float(ah));
    __nv_bfloat16 bl = __float2bfloat16(b - __bfloat162float(bh));
    hi = ((uint32_t)__bfloat16_as_ushort(bh) << 16) | (uint32_t)__bfloat16_as_ushort(ah);
    lo = ((uint32_t)__bfloat16_as_ushort(bl) << 16) | (uint32_t)__bfloat16_as_ushort(al);
}

#define MMA_BF16(d, a0, a1, a2, a3, b0v, b1v)                                 \
    asm volatile(                                                             \
        "mma.sync.aligned.m16n8k16.row.col.f32.bf16.bf16.f32 "                \
        "{%0,%1,%2,%3}, {%4,%5,%6,%7}, {%8,%9}, {%0,%1,%2,%3};"               \
        : "+f"((d)[0]), "+f"((d)[1]), "+f"((d)[2]), "+f"((d)[3])              \
        : "r"(a0), "r"(a1), "r"(a2), "r"(a3), "r"(b0v), "r"(b1v))

// ---------------------------------------------------------------------------
__global__ void prep_kernel(const float* __restrict__ lW1, const float* __restrict__ lW2,
                            const float* __restrict__ gW1, const float* __restrict__ gW2) {
    int tid = blockIdx.x * blockDim.x + threadIdx.x;     // 0..32767
    if (tid < S_SEG * 128) g_psum[tid] = 0.f;
    if (tid < S_SEG)       g_cnt[tid]  = 0.f;
    int m   = tid >> 13;
    int idx = tid & 8191;
    int n   = idx & 127;
    int kp  = idx >> 7;
    const float* src = (m == 0) ? lW1 : (m == 1) ? lW2 : (m == 2) ? gW1 : gW2;
    uint2*       dst = (m == 0) ? g_lW1p : (m == 1) ? g_lW2p : (m == 2) ? g_gW1p : g_gW2p;
    float a = src[(2 * kp) * 128 + n];
    float b = src[(2 * kp + 1) * 128 + n];
    uint32_t hi, lo;
    split2(a, b, hi, lo);
    dst[n * WSTRIDE + kp] = make_uint2(hi, lo);
}

__global__ void finalize_kernel() {
    int i = blockIdx.x * blockDim.x + threadIdx.x;
    if (i < S_SEG * 128)
        g_pooled[i] = g_psum[i] / fmaxf(g_cnt[i >> 7], 1.f);
}

// ---------------------------------------------------------------------------
// fused 2-layer MLP on a 128-row tile. 8 warps: (wm 0..3) x (wn 0..1),
// each warp owns out rows wm*32..+32, cols wn*64..+64.
// GAMMA=1: run-length segment-sum epilogue.  GAMMA=0: tanh(+pooled) output.
// ---------------------------------------------------------------------------
template <int GAMMA>
__global__ void __launch_bounds__(256)
mlp_kernel(const float* __restrict__ x, const int* __restrict__ seg,
           const float* __restrict__ b1g, const float* __restrict__ b2g,
           float* __restrict__ out, int nrows) {
    extern __shared__ char smem_raw[];
    SmemT& sm = *reinterpret_cast<SmemT*>(smem_raw);

    const uint2* __restrict__ W1g = GAMMA ? g_gW1p : g_lW1p;
    const uint2* __restrict__ W2g = GAMMA ? g_gW2p : g_lW2p;

    const int tid   = threadIdx.x;
    const int tile0 = blockIdx.x * 128;

    // ---- X tile: load + hi/lo split ----
    for (int i = tid; i < 128 * 32; i += 256) {
        int r  = i >> 5;
        int c4 = (i & 31) * 4;
        float4 v = make_float4(0.f, 0.f, 0.f, 0.f);
        if (tile0 + r < nrows)
            v = *reinterpret_cast<const float4*>(x + (size_t)(tile0 + r) * 128 + c4);
        uint32_t h0, l0, h1, l1;
        split2(v.x, v.y, h0, l0);
        split2(v.z, v.w, h1, l1);
        *reinterpret_cast<uint4*>(&sm.Xp[r * WSTRIDE + (c4 >> 1)]) = make_uint4(h0, l0, h1, l1);
    }
    {   // packed weights, linear copy
        const uint4* s1 = reinterpret_cast<const uint4*>(W1g);
        const uint4* s2 = reinterpret_cast<const uint4*>(W2g);
        uint4* d1 = reinterpret_cast<uint4*>(sm.W1p);
        uint4* d2 = reinterpret_cast<uint4*>(sm.W2p);
        for (int i = tid; i < 128 * WSTRIDE / 2; i += 256) { d1[i] = s1[i]; d2[i] = s2[i]; }
    }
    if (tid < 128) {
        sm.b1[tid]  = b1g[tid];
        sm.b2[tid]  = b2g[tid];
        sm.seg[tid] = (tile0 + tid < nrows) ? seg[tile0 + tid] : -1;
    }
    __syncthreads();

    const int lane = tid & 31, warp = tid >> 5;
    const int g = lane >> 2, t = lane & 3;
    const int wm = warp & 3, wn = warp >> 2;
    const int rbase = wm * 32;

    // ================= stage 1: H = relu(X@W1 + b1) =================
    float acc[2][8][4];
#pragma unroll
    for (int a = 0; a < 2; ++a)
#pragma unroll
        for (int b = 0; b < 8; ++b)
#pragma unroll
            for (int c = 0; c < 4; ++c) acc[a][b][c] = 0.f;

#pragma unroll
    for (int ks = 0; ks < 8; ++ks) {
        const int kp0 = ks * 8 + t;
        uint32_t Ah[2][4], Al[2][4];
#pragma unroll
        for (int mt = 0; mt < 2; ++mt) {
            int r0 = rbase + mt * 16 + g;
            uint2 q0 = sm.Xp[r0 * WSTRIDE + kp0];
            uint2 q1 = sm.Xp[(r0 + 8) * WSTRIDE + kp0];
            uint2 q2 = sm.Xp[r0 * WSTRIDE + kp0 + 4];
            uint2 q3 = sm.Xp[(r0 + 8) * WSTRIDE + kp0 + 4];
            Ah[mt][0] = q0.x; Al[mt][0] = q0.y;
            Ah[mt][1] = q1.x; Al[mt][1] = q1.y;
            Ah[mt][2] = q2.x; Al[mt][2] = q2.y;
            Ah[mt][3] = q3.x; Al[mt][3] = q3.y;
        }
#pragma unroll
        for (int nt = 0; nt < 8; ++nt) {
            int n = wn * 64 + nt * 8 + g;
            uint2 w0 = sm.W1p[n * WSTRIDE + kp0];
            uint2 w1 = sm.W1p[n * WSTRIDE + kp0 + 4];
#pragma unroll
            for (int mt = 0; mt < 2; ++mt) {
                MMA_BF16(acc[mt][nt], Ah[mt][0], Ah[mt][1], Ah[mt][2], Ah[mt][3], w0.x, w1.x);
                MMA_BF16(acc[mt][nt], Al[mt][0], Al[mt][1], Al[mt][2], Al[mt][3], w0.x, w1.x);
                MMA_BF16(acc[mt][nt], Ah[mt][0], Ah[mt][1], Ah[mt][2], Ah[mt][3], w0.y, w1.y);
            }
        }
    }
    __syncthreads();   // all W1p reads done before overwrite with H

    // relu + bias, repack into W1p region as H
    uint2* Hp = sm.W1p;
#pragma unroll
    for (int mt = 0; mt < 2; ++mt) {
#pragma unroll
        for (int nt = 0; nt < 8; ++nt) {
            int col = wn * 64 + nt * 8 + 2 * t;
            float bb0 = sm.b1[col], bb1 = sm.b1[col + 1];
            int r = rbase + mt * 16 + g;
            float h0 = fmaxf(acc[mt][nt][0] + bb0, 0.f);
            float h1 = fmaxf(acc[mt][nt][1] + bb1, 0.f);
            float h2 = fmaxf(acc[mt][nt][2] + bb0, 0.f);
            float h3 = fmaxf(acc[mt][nt][3] + bb1, 0.f);
            uint32_t hi, lo;
            split2(h0, h1, hi, lo);
            Hp[r * WSTRIDE + (col >> 1)] = make_uint2(hi, lo);
            split2(h2, h3, hi, lo);
            Hp[(r + 8) * WSTRIDE + (col >> 1)] = make_uint2(hi, lo);
        }
    }
    __syncthreads();

    // ================= stage 2: Y = H@W2 + b2 =================
#pragma unroll
    for (int a = 0; a < 2; ++a)
#pragma unroll
        for (int b = 0; b < 8; ++b)
#pragma unroll
            for (int c = 0; c < 4; ++c) acc[a][b][c] = 0.f;

#pragma unroll
    for (int ks = 0; ks < 8; ++ks) {
        const int kp0 = ks * 8 + t;
        uint32_t Ah[2][4], Al[2][4];
#pragma unroll
        for (int mt = 0; mt < 2; ++mt) {
            int r0 = rbase + mt * 16 + g;
            uint2 q0 = Hp[r0 * WSTRIDE + kp0];
            uint2 q1 = Hp[(r0 + 8) * WSTRIDE + kp0];
            uint2 q2 = Hp[r0 * WSTRIDE + kp0 + 4];
            uint2 q3 = Hp[(r0 + 8) * WSTRIDE + kp0 + 4];
            Ah[mt][0] = q0.x; Al[mt][0] = q0.y;
            Ah[mt][1] = q1.x; Al[mt][1] = q1.y;
            Ah[mt][2] = q2.x; Al[mt][2] = q2.y;
            Ah[mt][3] = q3.x; Al[mt][3] = q3.y;
        }
#pragma unroll
        for (int nt = 0; nt < 8; ++nt) {
            int n = wn * 64 + nt * 8 + g;
            uint2 w0 = sm.W2p[n * WSTRIDE + kp0];
            uint2 w1 = sm.W2p[n * WSTRIDE + kp0 + 4];
#pragma unroll
            for (int mt = 0; mt < 2; ++mt) {
                MMA_BF16(acc[mt][nt], Ah[mt][0], Ah[mt][1], Ah[mt][2], Ah[mt][3], w0.x, w1.x);
                MMA_BF16(acc[mt][nt], Al[mt][0], Al[mt][1], Al[mt][2], Al[mt][3], w0.x, w1.x);
                MMA_BF16(acc[mt][nt], Ah[mt][0], Ah[mt][1], Ah[mt][2], Ah[mt][3], w0.y, w1.y);
            }
        }
    }

    // Y (with bias) staged into the Xp region, stride 136 floats
    float* Y = reinterpret_cast<float*>(sm.Xp);
#pragma unroll
    for (int mt = 0; mt < 2; ++mt) {
#pragma unroll
        for (int nt = 0; nt < 8; ++nt) {
            int col = wn * 64 + nt * 8 + 2 * t;
            float bb0 = sm.b2[col], bb1 = sm.b2[col + 1];
            int r = rbase + mt * 16 + g;
            *reinterpret_cast<float2*>(&Y[r * 136 + col]) =
                make_float2(acc[mt][nt][0] + bb0, acc[mt][nt][1] + bb1);
            *reinterpret_cast<float2*>(&Y[(r + 8) * 136 + col]) =
                make_float2(acc[mt][nt][2] + bb0, acc[mt][nt][3] + bb1);
        }
    }
    __syncthreads();

    if (GAMMA) {
        // run-length segment-sum: thread = (col, half of rows)
        int c = tid & 127, half = tid >> 7;
        int r0 = half * 64, r1 = r0 + 64;
        float av = 0.f;
        int cur = sm.seg[r0];
        for (int r = r0; r < r1; ++r) {
            int s = sm.seg[r];
            if (s != cur) {
                if (cur >= 0) atomicAdd(&g_psum[cur * 128 + c], av);
                av = 0.f; cur = s;
            }
            av += Y[r * 136 + c];
        }
        if (cur >= 0) atomicAdd(&g_psum[cur * 128 + c], av);

        if (tid == 0) {
            int cur2 = sm.seg[0]; float run = 0.f;
            for (int r = 0; r < 128; ++r) {
                int s = sm.seg[r];
                if (s != cur2) {
                    if (cur2 >= 0) atomicAdd(&g_cnt[cur2], run);
                    run = 0.f; cur2 = s;
                }
                run += 1.f;
            }
            if (cur2 >= 0) atomicAdd(&g_cnt[cur2], run);
        }
    } else {
        // out = tanh(Y + pooled[seg]), coalesced float4
        for (int i = tid; i < 128 * 32; i += 256) {
            int r  = i >> 5;
            int c4 = (i & 31) * 4;
            if (tile0 + r < nrows) {
                int s = sm.seg[r];
                float4 p = *reinterpret_cast<const float4*>(&g_pooled[s * 128 + c4]);
                float4 yv = *reinterpret_cast<const float4*>(&Y[r * 136 + c4]);
                float4 o;
                o.x = tanhf(yv.x + p.x);
                o.y = tanhf(yv.y + p.y);
                o.z = tanhf(yv.z + p.z);
                o.w = tanhf(yv.w + p.w);
                *reinterpret_cast<float4*>(out + (size_t)(tile0 + r) * 128 + c4) = o;
            }
        }
    }
}

// ---------------------------------------------------------------------------
extern "C" void kernel_launch(void* const* d_in, const int* in_sizes, int n_in,
                              void* d_out, int out_size) {
    const float* x    = (const float*)d_in[0];
    const int*   seg  = (const int*)d_in[1];
    const float* lW1  = (const float*)d_in[2];
    const float* lb1  = (const float*)d_in[3];
    const float* lW2  = (const float*)d_in[4];
    const float* lb2  = (const float*)d_in[5];
    const float* gW1  = (const float*)d_in[6];
    const float* gb1  = (const float*)d_in[7];
    const float* gW2  = (const float*)d_in[8];
    const float* gb2  = (const float*)d_in[9];

    int nrows = in_sizes[0] / 128;
    int tiles = (nrows + 127) / 128;
    size_t smem = sizeof(SmemT);

    cudaFuncSetAttribute(mlp_kernel<1>, cudaFuncAttributeMaxDynamicSharedMemorySize, (int)smem);
    cudaFuncSetAttribute(mlp_kernel<0>, cudaFuncAttributeMaxDynamicSharedMemorySize, (int)smem);

    prep_kernel<<<128, 256>>>(lW1, lW2, gW1, gW2);
    mlp_kernel<1><<<tiles, 256, smem>>>(x, seg, gb1, gb2, nullptr, nrows);
    finalize_kernel<<<128, 256>>>();
    mlp_kernel<0><<<tiles, 256, smem>>>(x, seg, lb1, lb2, (float*)d_out, nrows);
}

// round 4
// speedup vs baseline: 1.2980x; 1.2980x over previous
#include <cuda_runtime.h>
#include <cuda_bf16.h>
#include <math.h>
#include <stdint.h>

#define S_SEG 256
#define WSTRIDE 68   // uint2 stride for packed [128 x 64-pair] tiles

// ---- global scratch (no allocs allowed) ----
__device__ uint2 g_lW1p[128 * WSTRIDE];
__device__ uint2 g_lW2p[128 * WSTRIDE];
__device__ uint2 g_gW1p[128 * WSTRIDE];
__device__ uint2 g_gW2p[128 * WSTRIDE];
__device__ float g_psum[S_SEG * 128];
__device__ float g_cnt[S_SEG];
__device__ float g_pooled[S_SEG * 128];

struct SmemT {
    uint2 Xp[128 * WSTRIDE];    // X packed; later reused as float Y[128*136]
    uint2 W1p[128 * WSTRIDE];   // W1 packed; later reused as H packed
    uint2 W2p[128 * WSTRIDE];
    float b1[128];
    float b2[128];
    int   seg[128];
};  // ~210 KB -> 1 CTA/SM

__device__ __forceinline__ void split2(float a, float b, uint32_t& hi, uint32_t& lo) {
    __nv_bfloat16 ah = __float2bfloat16(a);
    __nv_bfloat16 bh = __float2bfloat16(b);
    __nv_bfloat16 al = __float2bfloat16(a - __bfloat162float(ah));
    __nv_bfloat16 bl = __float2bfloat16(b - __bfloat162float(bh));
    hi = ((uint32_t)__bfloat16_as_ushort(bh) << 16) | (uint32_t)__bfloat16_as_ushort(ah);
    lo = ((uint32_t)__bfloat16_as_ushort(bl) << 16) | (uint32_t)__bfloat16_as_ushort(al);
}

#define MMA_BF16(d, a0, a1, a2, a3, b0v, b1v)                                 \
    asm volatile(                                                             \
        "mma.sync.aligned.m16n8k16.row.col.f32.bf16.bf16.f32 "                \
        "{%0,%1,%2,%3}, {%4,%5,%6,%7}, {%8,%9}, {%0,%1,%2,%3};"               \
        : "+f"((d)[0]), "+f"((d)[1]), "+f"((d)[2]), "+f"((d)[3])              \
        : "r"(a0), "r"(a1), "r"(a2), "r"(a3), "r"(b0v), "r"(b1v))

// ---------------------------------------------------------------------------
__global__ void prep_kernel(const float* __restrict__ lW1, const float* __restrict__ lW2,
                            const float* __restrict__ gW1, const float* __restrict__ gW2) {
    int tid = blockIdx.x * blockDim.x + threadIdx.x;     // 0..32767
    if (tid < S_SEG * 128) g_psum[tid] = 0.f;
    if (tid < S_SEG)       g_cnt[tid]  = 0.f;
    int m   = tid >> 13;
    int idx = tid & 8191;
    int n   = idx & 127;
    int kp  = idx >> 7;
    const float* src = (m == 0) ? lW1 : (m == 1) ? lW2 : (m == 2) ? gW1 : gW2;
    uint2*       dst = (m == 0) ? g_lW1p : (m == 1) ? g_lW2p : (m == 2) ? g_gW1p : g_gW2p;
    float a = src[(2 * kp) * 128 + n];
    float b = src[(2 * kp + 1) * 128 + n];
    uint32_t hi, lo;
    split2(a, b, hi, lo);
    dst[n * WSTRIDE + kp] = make_uint2(hi, lo);
}

__global__ void finalize_kernel() {
    int i = blockIdx.x * blockDim.x + threadIdx.x;
    if (i < S_SEG * 128)
        g_pooled[i] = g_psum[i] / fmaxf(g_cnt[i >> 7], 1.f);
}

// ---------------------------------------------------------------------------
// fused 2-layer MLP on a 128-row tile. 16 warps: (wm 0..3) x (wn 0..3),
// each warp owns out rows wm*32..+32, cols wn*32..+32.
// GAMMA=1: run-length segment-sum epilogue.  GAMMA=0: tanh(+pooled) output.
// ---------------------------------------------------------------------------
template <int GAMMA>
__global__ void __launch_bounds__(512)
mlp_kernel(const float* __restrict__ x, const int* __restrict__ seg,
           const float* __restrict__ b1g, const float* __restrict__ b2g,
           float* __restrict__ out, int nrows) {
    extern __shared__ char smem_raw[];
    SmemT& sm = *reinterpret_cast<SmemT*>(smem_raw);

    const uint2* __restrict__ W1g = GAMMA ? g_gW1p : g_lW1p;
    const uint2* __restrict__ W2g = GAMMA ? g_gW2p : g_lW2p;

    const int tid   = threadIdx.x;
    const int tile0 = blockIdx.x * 128;

    // ---- X tile: load + hi/lo split ----
    for (int i = tid; i < 128 * 32; i += 512) {
        int r  = i >> 5;
        int c4 = (i & 31) * 4;
        float4 v = make_float4(0.f, 0.f, 0.f, 0.f);
        if (tile0 + r < nrows)
            v = *reinterpret_cast<const float4*>(x + (size_t)(tile0 + r) * 128 + c4);
        uint32_t h0, l0, h1, l1;
        split2(v.x, v.y, h0, l0);
        split2(v.z, v.w, h1, l1);
        *reinterpret_cast<uint4*>(&sm.Xp[r * WSTRIDE + (c4 >> 1)]) = make_uint4(h0, l0, h1, l1);
    }
    {   // packed weights, linear copy
        const uint4* s1 = reinterpret_cast<const uint4*>(W1g);
        const uint4* s2 = reinterpret_cast<const uint4*>(W2g);
        uint4* d1 = reinterpret_cast<uint4*>(sm.W1p);
        uint4* d2 = reinterpret_cast<uint4*>(sm.W2p);
        for (int i = tid; i < 128 * WSTRIDE / 2; i += 512) { d1[i] = s1[i]; d2[i] = s2[i]; }
    }
    if (tid < 128) {
        sm.b1[tid]  = b1g[tid];
        sm.b2[tid]  = b2g[tid];
        sm.seg[tid] = (tile0 + tid < nrows) ? seg[tile0 + tid] : -1;
    }
    __syncthreads();

    const int lane = tid & 31, warp = tid >> 5;
    const int g = lane >> 2, t = lane & 3;
    const int wm = warp & 3, wn = warp >> 2;          // 4 x 4 warp grid
    const int rbase = wm * 32;

    // ================= stage 1: H = relu(X@W1 + b1) =================
    float acc[2][4][4];
#pragma unroll
    for (int a = 0; a < 2; ++a)
#pragma unroll
        for (int b = 0; b < 4; ++b)
#pragma unroll
            for (int c = 0; c < 4; ++c) acc[a][b][c] = 0.f;

#pragma unroll
    for (int ks = 0; ks < 8; ++ks) {
        const int kp0 = ks * 8 + t;
        uint32_t Ah[2][4], Al[2][4];
#pragma unroll
        for (int mt = 0; mt < 2; ++mt) {
            int r0 = rbase + mt * 16 + g;
            uint2 q0 = sm.Xp[r0 * WSTRIDE + kp0];
            uint2 q1 = sm.Xp[(r0 + 8) * WSTRIDE + kp0];
            uint2 q2 = sm.Xp[r0 * WSTRIDE + kp0 + 4];
            uint2 q3 = sm.Xp[(r0 + 8) * WSTRIDE + kp0 + 4];
            Ah[mt][0] = q0.x; Al[mt][0] = q0.y;
            Ah[mt][1] = q1.x; Al[mt][1] = q1.y;
            Ah[mt][2] = q2.x; Al[mt][2] = q2.y;
            Ah[mt][3] = q3.x; Al[mt][3] = q3.y;
        }
#pragma unroll
        for (int nt = 0; nt < 4; ++nt) {
            int n = wn * 32 + nt * 8 + g;
            uint2 w0 = sm.W1p[n * WSTRIDE + kp0];
            uint2 w1 = sm.W1p[n * WSTRIDE + kp0 + 4];
#pragma unroll
            for (int mt = 0; mt < 2; ++mt) {
                MMA_BF16(acc[mt][nt], Ah[mt][0], Ah[mt][1], Ah[mt][2], Ah[mt][3], w0.x, w1.x);
                MMA_BF16(acc[mt][nt], Al[mt][0], Al[mt][1], Al[mt][2], Al[mt][3], w0.x, w1.x);
                MMA_BF16(acc[mt][nt], Ah[mt][0], Ah[mt][1], Ah[mt][2], Ah[mt][3], w0.y, w1.y);
            }
        }
    }
    __syncthreads();   // all W1p reads done before overwrite with H

    // relu + bias, repack into W1p region as H
    uint2* Hp = sm.W1p;
#pragma unroll
    for (int mt = 0; mt < 2; ++mt) {
#pragma unroll
        for (int nt = 0; nt < 4; ++nt) {
            int col = wn * 32 + nt * 8 + 2 * t;
            float bb0 = sm.b1[col], bb1 = sm.b1[col + 1];
            int r = rbase + mt * 16 + g;
            float h0 = fmaxf(acc[mt][nt][0] + bb0, 0.f);
            float h1 = fmaxf(acc[mt][nt][1] + bb1, 0.f);
            float h2 = fmaxf(acc[mt][nt][2] + bb0, 0.f);
            float h3 = fmaxf(acc[mt][nt][3] + bb1, 0.f);
            uint32_t hi, lo;
            split2(h0, h1, hi, lo);
            Hp[r * WSTRIDE + (col >> 1)] = make_uint2(hi, lo);
            split2(h2, h3, hi, lo);
            Hp[(r + 8) * WSTRIDE + (col >> 1)] = make_uint2(hi, lo);
        }
    }
    __syncthreads();

    // ================= stage 2: Y = H@W2 + b2 =================
#pragma unroll
    for (int a = 0; a < 2; ++a)
#pragma unroll
        for (int b = 0; b < 4; ++b)
#pragma unroll
            for (int c = 0; c < 4; ++c) acc[a][b][c] = 0.f;

#pragma unroll
    for (int ks = 0; ks < 8; ++ks) {
        const int kp0 = ks * 8 + t;
        uint32_t Ah[2][4], Al[2][4];
#pragma unroll
        for (int mt = 0; mt < 2; ++mt) {
            int r0 = rbase + mt * 16 + g;
            uint2 q0 = Hp[r0 * WSTRIDE + kp0];
            uint2 q1 = Hp[(r0 + 8) * WSTRIDE + kp0];
            uint2 q2 = Hp[r0 * WSTRIDE + kp0 + 4];
            uint2 q3 = Hp[(r0 + 8) * WSTRIDE + kp0 + 4];
            Ah[mt][0] = q0.x; Al[mt][0] = q0.y;
            Ah[mt][1] = q1.x; Al[mt][1] = q1.y;
            Ah[mt][2] = q2.x; Al[mt][2] = q2.y;
            Ah[mt][3] = q3.x; Al[mt][3] = q3.y;
        }
#pragma unroll
        for (int nt = 0; nt < 4; ++nt) {
            int n = wn * 32 + nt * 8 + g;
            uint2 w0 = sm.W2p[n * WSTRIDE + kp0];
            uint2 w1 = sm.W2p[n * WSTRIDE + kp0 + 4];
#pragma unroll
            for (int mt = 0; mt < 2; ++mt) {
                MMA_BF16(acc[mt][nt], Ah[mt][0], Ah[mt][1], Ah[mt][2], Ah[mt][3], w0.x, w1.x);
                MMA_BF16(acc[mt][nt], Al[mt][0], Al[mt][1], Al[mt][2], Al[mt][3], w0.x, w1.x);
                MMA_BF16(acc[mt][nt], Ah[mt][0], Ah[mt][1], Ah[mt][2], Ah[mt][3], w0.y, w1.y);
            }
        }
    }

    // Y (with bias) staged into the Xp region, stride 136 floats
    float* Y = reinterpret_cast<float*>(sm.Xp);
#pragma unroll
    for (int mt = 0; mt < 2; ++mt) {
#pragma unroll
        for (int nt = 0; nt < 4; ++nt) {
            int col = wn * 32 + nt * 8 + 2 * t;
            float bb0 = sm.b2[col], bb1 = sm.b2[col + 1];
            int r = rbase + mt * 16 + g;
            *reinterpret_cast<float2*>(&Y[r * 136 + col]) =
                make_float2(acc[mt][nt][0] + bb0, acc[mt][nt][1] + bb1);
            *reinterpret_cast<float2*>(&Y[(r + 8) * 136 + col]) =
                make_float2(acc[mt][nt][2] + bb0, acc[mt][nt][3] + bb1);
        }
    }
    __syncthreads();

    if (GAMMA) {
        // run-length segment-sum: thread = (col, quarter of rows)
        int c = tid & 127, quarter = tid >> 7;      // 512 threads = 128 cols x 4
        int r0 = quarter * 32, r1 = r0 + 32;
        float av = 0.f;
        int cur = sm.seg[r0];
        for (int r = r0; r < r1; ++r) {
            int s = sm.seg[r];
            if (s != cur) {
                if (cur >= 0) atomicAdd(&g_psum[cur * 128 + c], av);
                av = 0.f; cur = s;
            }
            av += Y[r * 136 + c];
        }
        if (cur >= 0) atomicAdd(&g_psum[cur * 128 + c], av);

        if (tid == 0) {
            int cur2 = sm.seg[0]; float run = 0.f;
            for (int r = 0; r < 128; ++r) {
                int s = sm.seg[r];
                if (s != cur2) {
                    if (cur2 >= 0) atomicAdd(&g_cnt[cur2], run);
                    run = 0.f; cur2 = s;
                }
                run += 1.f;
            }
            if (cur2 >= 0) atomicAdd(&g_cnt[cur2], run);
        }
    } else {
        // out = tanh(Y + pooled[seg]), coalesced float4
        for (int i = tid; i < 128 * 32; i += 512) {
            int r  = i >> 5;
            int c4 = (i & 31) * 4;
            if (tile0 + r < nrows) {
                int s = sm.seg[r];
                float4 p = *reinterpret_cast<const float4*>(&g_pooled[s * 128 + c4]);
                float4 yv = *reinterpret_cast<const float4*>(&Y[r * 136 + c4]);
                float4 o;
                o.x = tanhf(yv.x + p.x);
                o.y = tanhf(yv.y + p.y);
                o.z = tanhf(yv.z + p.z);
                o.w = tanhf(yv.w + p.w);
                *reinterpret_cast<float4*>(out + (size_t)(tile0 + r) * 128 + c4) = o;
            }
        }
    }
}

// ---------------------------------------------------------------------------
extern "C" void kernel_launch(void* const* d_in, const int* in_sizes, int n_in,
                              void* d_out, int out_size) {
    const float* x    = (const float*)d_in[0];
    const int*   seg  = (const int*)d_in[1];
    const float* lW1  = (const float*)d_in[2];
    const float* lb1  = (const float*)d_in[3];
    const float* lW2  = (const float*)d_in[4];
    const float* lb2  = (const float*)d_in[5];
    const float* gW1  = (const float*)d_in[6];
    const float* gb1  = (const float*)d_in[7];
    const float* gW2  = (const float*)d_in[8];
    const float* gb2  = (const float*)d_in[9];

    int nrows = in_sizes[0] / 128;
    int tiles = (nrows + 127) / 128;
    size_t smem = sizeof(SmemT);

    cudaFuncSetAttribute(mlp_kernel<1>, cudaFuncAttributeMaxDynamicSharedMemorySize, (int)smem);
    cudaFuncSetAttribute(mlp_kernel<0>, cudaFuncAttributeMaxDynamicSharedMemorySize, (int)smem);

    prep_kernel<<<128, 256>>>(lW1, lW2, gW1, gW2);
    mlp_kernel<1><<<tiles, 512, smem>>>(x, seg, gb1, gb2, nullptr, nrows);
    finalize_kernel<<<128, 256>>>();
    mlp_kernel<0><<<tiles, 512, smem>>>(x, seg, lb1, lb2, (float*)d_out, nrows);
}

// round 5
// speedup vs baseline: 1.4052x; 1.0825x over previous
#include <cuda_runtime.h>
#include <cuda_bf16.h>
#include <math.h>
#include <stdint.h>

#define S_SEG 256
#define WSTRIDE 68    // uint2 stride for packed [rows x 64-pair] tiles
#define TROWS 192     // rows per CTA tile
#define NTHREADS 768  // 24 warps: (wm 0..5) x (wn 0..3), warp tile 32x32

// ---- global scratch (no allocs allowed) ----
__device__ uint2 g_lW1p[128 * WSTRIDE];
__device__ uint2 g_lW2p[128 * WSTRIDE];
__device__ uint2 g_gW1p[128 * WSTRIDE];
__device__ uint2 g_gW2p[128 * WSTRIDE];
__device__ float g_psum[S_SEG * 128];
__device__ float g_cnt[S_SEG];
__device__ float g_pooled[S_SEG * 128];

struct SmemT {
    uint2 Ap[TROWS * WSTRIDE];  // X packed -> H packed -> float Y[TROWS*136]
    uint2 Wp[128 * WSTRIDE];    // W1 packed, then reloaded with W2 packed
    float b1[128];
    float b2[128];
    int   seg[TROWS];
};  // 104448 + 69632 + 512 + 512 + 768 = 175872 B -> 1 CTA/SM, 24 warps

__device__ __forceinline__ void split2(float a, float b, uint32_t& hi, uint32_t& lo) {
    __nv_bfloat16 ah = __float2bfloat16(a);
    __nv_bfloat16 bh = __float2bfloat16(b);
    __nv_bfloat16 al = __float2bfloat16(a - __bfloat162float(ah));
    __nv_bfloat16 bl = __float2bfloat16(b - __bfloat162float(bh));
    hi = ((uint32_t)__bfloat16_as_ushort(bh) << 16) | (uint32_t)__bfloat16_as_ushort(ah);
    lo = ((uint32_t)__bfloat16_as_ushort(bl) << 16) | (uint32_t)__bfloat16_as_ushort(al);
}

#define MMA_BF16(d, a0, a1, a2, a3, b0v, b1v)                                 \
    asm volatile(                                                             \
        "mma.sync.aligned.m16n8k16.row.col.f32.bf16.bf16.f32 "                \
        "{%0,%1,%2,%3}, {%4,%5,%6,%7}, {%8,%9}, {%0,%1,%2,%3};"               \
        : "+f"((d)[0]), "+f"((d)[1]), "+f"((d)[2]), "+f"((d)[3])              \
        : "r"(a0), "r"(a1), "r"(a2), "r"(a3), "r"(b0v), "r"(b1v))

// ---------------------------------------------------------------------------
__global__ void prep_kernel(const float* __restrict__ lW1, const float* __restrict__ lW2,
                            const float* __restrict__ gW1, const float* __restrict__ gW2) {
    int tid = blockIdx.x * blockDim.x + threadIdx.x;     // 0..32767
    if (tid < S_SEG * 128) g_psum[tid] = 0.f;
    if (tid < S_SEG)       g_cnt[tid]  = 0.f;
    int m   = tid >> 13;
    int idx = tid & 8191;
    int n   = idx & 127;
    int kp  = idx >> 7;
    const float* src = (m == 0) ? lW1 : (m == 1) ? lW2 : (m == 2) ? gW1 : gW2;
    uint2*       dst = (m == 0) ? g_lW1p : (m == 1) ? g_lW2p : (m == 2) ? g_gW1p : g_gW2p;
    float a = src[(2 * kp) * 128 + n];
    float b = src[(2 * kp + 1) * 128 + n];
    uint32_t hi, lo;
    split2(a, b, hi, lo);
    dst[n * WSTRIDE + kp] = make_uint2(hi, lo);
}

__global__ void finalize_kernel() {
    int i = blockIdx.x * blockDim.x + threadIdx.x;
    if (i < S_SEG * 128)
        g_pooled[i] = g_psum[i] / fmaxf(g_cnt[i >> 7], 1.f);
}

// ---------------------------------------------------------------------------
// fused 2-layer MLP on a 192-row tile. 24 warps: (wm 0..5) x (wn 0..3),
// warp tile 32x32. GAMMA=1: run-length segment-sum. GAMMA=0: tanh(+pooled).
// ---------------------------------------------------------------------------
template <int GAMMA>
__global__ void __launch_bounds__(NTHREADS)
mlp_kernel(const float* __restrict__ x, const int* __restrict__ seg,
           const float* __restrict__ b1g, const float* __restrict__ b2g,
           float* __restrict__ out, int nrows) {
    extern __shared__ char smem_raw[];
    SmemT& sm = *reinterpret_cast<SmemT*>(smem_raw);

    const uint2* __restrict__ W1g = GAMMA ? g_gW1p : g_lW1p;
    const uint2* __restrict__ W2g = GAMMA ? g_gW2p : g_lW2p;

    const int tid   = threadIdx.x;
    const int tile0 = blockIdx.x * TROWS;

    // ---- X tile: load + hi/lo split ----
    for (int i = tid; i < TROWS * 32; i += NTHREADS) {
        int r  = i >> 5;
        int c4 = (i & 31) * 4;
        float4 v = make_float4(0.f, 0.f, 0.f, 0.f);
        if (tile0 + r < nrows)
            v = *reinterpret_cast<const float4*>(x + (size_t)(tile0 + r) * 128 + c4);
        uint32_t h0, l0, h1, l1;
        split2(v.x, v.y, h0, l0);
        split2(v.z, v.w, h1, l1);
        *reinterpret_cast<uint4*>(&sm.Ap[r * WSTRIDE + (c4 >> 1)]) = make_uint4(h0, l0, h1, l1);
    }
    {   // W1 packed -> smem (linear copy)
        const uint4* s1 = reinterpret_cast<const uint4*>(W1g);
        uint4* d1 = reinterpret_cast<uint4*>(sm.Wp);
        for (int i = tid; i < 128 * WSTRIDE / 2; i += NTHREADS) d1[i] = s1[i];
    }
    if (tid < 128) {
        sm.b1[tid] = b1g[tid];
        sm.b2[tid] = b2g[tid];
    }
    if (tid < TROWS)
        sm.seg[tid] = (tile0 + tid < nrows) ? seg[tile0 + tid] : -1;
    __syncthreads();

    const int lane = tid & 31, warp = tid >> 5;
    const int g = lane >> 2, t = lane & 3;
    const int wm = warp >> 2, wn = warp & 3;   // 6 x 4 warp grid
    const int rbase = wm * 32;

    // ================= stage 1: H = relu(X@W1 + b1) =================
    float acc[2][4][4];
#pragma unroll
    for (int a = 0; a < 2; ++a)
#pragma unroll
        for (int b = 0; b < 4; ++b)
#pragma unroll
            for (int c = 0; c < 4; ++c) acc[a][b][c] = 0.f;

#pragma unroll
    for (int ks = 0; ks < 8; ++ks) {
        const int kp0 = ks * 8 + t;
        uint32_t Ah[2][4], Al[2][4];
#pragma unroll
        for (int mt = 0; mt < 2; ++mt) {
            int r0 = rbase + mt * 16 + g;
            uint2 q0 = sm.Ap[r0 * WSTRIDE + kp0];
            uint2 q1 = sm.Ap[(r0 + 8) * WSTRIDE + kp0];
            uint2 q2 = sm.Ap[r0 * WSTRIDE + kp0 + 4];
            uint2 q3 = sm.Ap[(r0 + 8) * WSTRIDE + kp0 + 4];
            Ah[mt][0] = q0.x; Al[mt][0] = q0.y;
            Ah[mt][1] = q1.x; Al[mt][1] = q1.y;
            Ah[mt][2] = q2.x; Al[mt][2] = q2.y;
            Ah[mt][3] = q3.x; Al[mt][3] = q3.y;
        }
#pragma unroll
        for (int nt = 0; nt < 4; ++nt) {
            int n = wn * 32 + nt * 8 + g;
            uint2 w0 = sm.Wp[n * WSTRIDE + kp0];
            uint2 w1 = sm.Wp[n * WSTRIDE + kp0 + 4];
#pragma unroll
            for (int mt = 0; mt < 2; ++mt) {
                MMA_BF16(acc[mt][nt], Ah[mt][0], Ah[mt][1], Ah[mt][2], Ah[mt][3], w0.x, w1.x);
                MMA_BF16(acc[mt][nt], Al[mt][0], Al[mt][1], Al[mt][2], Al[mt][3], w0.x, w1.x);
                MMA_BF16(acc[mt][nt], Ah[mt][0], Ah[mt][1], Ah[mt][2], Ah[mt][3], w0.y, w1.y);
            }
        }
    }
    __syncthreads();   // X reads done (Ap free), W1 reads done (Wp free)

    // relu + bias -> H packed into Ap; meanwhile reload Wp with W2
    {
        const uint4* s2 = reinterpret_cast<const uint4*>(W2g);
        uint4* d2 = reinterpret_cast<uint4*>(sm.Wp);
        for (int i = tid; i < 128 * WSTRIDE / 2; i += NTHREADS) d2[i] = s2[i];
    }
    uint2* Hp = sm.Ap;
#pragma unroll
    for (int mt = 0; mt < 2; ++mt) {
#pragma unroll
        for (int nt = 0; nt < 4; ++nt) {
            int col = wn * 32 + nt * 8 + 2 * t;
            float bb0 = sm.b1[col], bb1 = sm.b1[col + 1];
            int r = rbase + mt * 16 + g;
            float h0 = fmaxf(acc[mt][nt][0] + bb0, 0.f);
            float h1 = fmaxf(acc[mt][nt][1] + bb1, 0.f);
            float h2 = fmaxf(acc[mt][nt][2] + bb0, 0.f);
            float h3 = fmaxf(acc[mt][nt][3] + bb1, 0.f);
            uint32_t hi, lo;
            split2(h0, h1, hi, lo);
            Hp[r * WSTRIDE + (col >> 1)] = make_uint2(hi, lo);
            split2(h2, h3, hi, lo);
            Hp[(r + 8) * WSTRIDE + (col >> 1)] = make_uint2(hi, lo);
        }
    }
    __syncthreads();

    // ================= stage 2: Y = H@W2 + b2 =================
#pragma unroll
    for (int a = 0; a < 2; ++a)
#pragma unroll
        for (int b = 0; b < 4; ++b)
#pragma unroll
            for (int c = 0; c < 4; ++c) acc[a][b][c] = 0.f;

#pragma unroll
    for (int ks = 0; ks < 8; ++ks) {
        const int kp0 = ks * 8 + t;
        uint32_t Ah[2][4], Al[2][4];
#pragma unroll
        for (int mt = 0; mt < 2; ++mt) {
            int r0 = rbase + mt * 16 + g;
            uint2 q0 = Hp[r0 * WSTRIDE + kp0];
            uint2 q1 = Hp[(r0 + 8) * WSTRIDE + kp0];
            uint2 q2 = Hp[r0 * WSTRIDE + kp0 + 4];
            uint2 q3 = Hp[(r0 + 8) * WSTRIDE + kp0 + 4];
            Ah[mt][0] = q0.x; Al[mt][0] = q0.y;
            Ah[mt][1] = q1.x; Al[mt][1] = q1.y;
            Ah[mt][2] = q2.x; Al[mt][2] = q2.y;
            Ah[mt][3] = q3.x; Al[mt][3] = q3.y;
        }
#pragma unroll
        for (int nt = 0; nt < 4; ++nt) {
            int n = wn * 32 + nt * 8 + g;
            uint2 w0 = sm.Wp[n * WSTRIDE + kp0];
            uint2 w1 = sm.Wp[n * WSTRIDE + kp0 + 4];
#pragma unroll
            for (int mt = 0; mt < 2; ++mt) {
                MMA_BF16(acc[mt][nt], Ah[mt][0], Ah[mt][1], Ah[mt][2], Ah[mt][3], w0.x, w1.x);
                MMA_BF16(acc[mt][nt], Al[mt][0], Al[mt][1], Al[mt][2], Al[mt][3], w0.x, w1.x);
                MMA_BF16(acc[mt][nt], Ah[mt][0], Ah[mt][1], Ah[mt][2], Ah[mt][3], w0.y, w1.y);
            }
        }
    }
    __syncthreads();   // all H reads done -> Ap free for Y

    // Y (with bias) staged into Ap region, stride 136 floats
    float* Y = reinterpret_cast<float*>(sm.Ap);
#pragma unroll
    for (int mt = 0; mt < 2; ++mt) {
#pragma unroll
        for (int nt = 0; nt < 4; ++nt) {
            int col = wn * 32 + nt * 8 + 2 * t;
            float bb0 = sm.b2[col], bb1 = sm.b2[col + 1];
            int r = rbase + mt * 16 + g;
            *reinterpret_cast<float2*>(&Y[r * 136 + col]) =
                make_float2(acc[mt][nt][0] + bb0, acc[mt][nt][1] + bb1);
            *reinterpret_cast<float2*>(&Y[(r + 8) * 136 + col]) =
                make_float2(acc[mt][nt][2] + bb0, acc[mt][nt][3] + bb1);
        }
    }
    __syncthreads();

    if (GAMMA) {
        // run-length segment-sum: thread = (col, sixth of rows)
        int c = tid & 127, part = tid >> 7;       // 768 threads = 128 cols x 6 parts
        int r0 = part * 32, r1 = r0 + 32;
        float av = 0.f;
        int cur = sm.seg[r0];
        for (int r = r0; r < r1; ++r) {
            int s = sm.seg[r];
            if (s != cur) {
                if (cur >= 0) atomicAdd(&g_psum[cur * 128 + c], av);
                av = 0.f; cur = s;
            }
            av += Y[r * 136 + c];
        }
        if (cur >= 0) atomicAdd(&g_psum[cur * 128 + c], av);

        if (tid == 0) {
            int cur2 = sm.seg[0]; float run = 0.f;
            for (int r = 0; r < TROWS; ++r) {
                int s = sm.seg[r];
                if (s != cur2) {
                    if (cur2 >= 0) atomicAdd(&g_cnt[cur2], run);
                    run = 0.f; cur2 = s;
                }
                run += 1.f;
            }
            if (cur2 >= 0) atomicAdd(&g_cnt[cur2], run);
        }
    } else {
        // out = tanh(Y + pooled[seg]), coalesced float4
        for (int i = tid; i < TROWS * 32; i += NTHREADS) {
            int r  = i >> 5;
            int c4 = (i & 31) * 4;
            if (tile0 + r < nrows) {
                int s = sm.seg[r];
                float4 p = *reinterpret_cast<const float4*>(&g_pooled[s * 128 + c4]);
                float4 yv = *reinterpret_cast<const float4*>(&Y[r * 136 + c4]);
                float4 o;
                o.x = tanhf(yv.x + p.x);
                o.y = tanhf(yv.y + p.y);
                o.z = tanhf(yv.z + p.z);
                o.w = tanhf(yv.w + p.w);
                *reinterpret_cast<float4*>(out + (size_t)(tile0 + r) * 128 + c4) = o;
            }
        }
    }
}

// ---------------------------------------------------------------------------
extern "C" void kernel_launch(void* const* d_in, const int* in_sizes, int n_in,
                              void* d_out, int out_size) {
    const float* x    = (const float*)d_in[0];
    const int*   seg  = (const int*)d_in[1];
    const float* lW1  = (const float*)d_in[2];
    const float* lb1  = (const float*)d_in[3];
    const float* lW2  = (const float*)d_in[4];
    const float* lb2  = (const float*)d_in[5];
    const float* gW1  = (const float*)d_in[6];
    const float* gb1  = (const float*)d_in[7];
    const float* gW2  = (const float*)d_in[8];
    const float* gb2  = (const float*)d_in[9];

    int nrows = in_sizes[0] / 128;
    int tiles = (nrows + TROWS - 1) / TROWS;
    size_t smem = sizeof(SmemT);

    cudaFuncSetAttribute(mlp_kernel<1>, cudaFuncAttributeMaxDynamicSharedMemorySize, (int)smem);
    cudaFuncSetAttribute(mlp_kernel<0>, cudaFuncAttributeMaxDynamicSharedMemorySize, (int)smem);

    prep_kernel<<<128, 256>>>(lW1, lW2, gW1, gW2);
    mlp_kernel<1><<<tiles, NTHREADS, smem>>>(x, seg, gb1, gb2, nullptr, nrows);
    finalize_kernel<<<128, 256>>>();
    mlp_kernel<0><<<tiles, NTHREADS, smem>>>(x, seg, lb1, lb2, (float*)d_out, nrows);
}